// round 4
// baseline (speedup 1.0000x reference)
#include <cuda_runtime.h>

// Shapes fixed by reference setup_inputs()
#define BB      16
#define NPTS    1024          // H*W
#define DD      128           // = 32 float4 chunks
#define KK      32
#define GPB     16            // chunks (CTAs) per batch
#define PPB     (NPTS / GPB)  // 64 points per CTA
#define NTHREADS 256
#define NCHUNK  (BB * GPB)    // 256

// Shared layout: xs[64][33] f4 | cs[32][34] f4 | As[64][33] f | x2s[64] f
#define XS_STRIDE 33
#define CS_STRIDE 34
#define AS_STRIDE 33
#define XS_BYTES  (PPB * XS_STRIDE * 16)            // 33792
#define CS_BYTES  (KK * CS_STRIDE * 16)             // 17408
#define AS_BYTES  (PPB * AS_STRIDE * 4)             // 8448
#define SMEM_BYTES (XS_BYTES + CS_BYTES + AS_BYTES + PPB * 4)  // 59904

// Cross-CTA partial tiles: [chunk][d][k] (coalesced STG + vectorizable LDG over k)
__device__ float4 g_Ep4[NCHUNK * KK * DD / 4];      // 4 MB scratch, 16B aligned
__device__ int    g_cnt[BB];                        // per-batch arrival counters (zero-init)

__device__ __forceinline__ unsigned long long ffma2_(unsigned long long a,
                                                     unsigned long long b,
                                                     unsigned long long c) {
    unsigned long long d;
    asm("fma.rn.f32x2 %0, %1, %2, %3;" : "=l"(d) : "l"(a), "l"(b), "l"(c));
    return d;
}
__device__ __forceinline__ unsigned long long pack2(float lo, float hi) {
    unsigned long long r;
    asm("mov.b64 %0, {%1, %2};" : "=l"(r) : "f"(lo), "f"(hi));
    return r;
}
__device__ __forceinline__ float2 unpack2(unsigned long long v) {
    float2 r;
    asm("mov.b64 {%0, %1}, %2;" : "=f"(r.x), "=f"(r.y) : "l"(v));
    return r;
}

__global__ __launch_bounds__(NTHREADS, 2)
void ev_encode_kernel(const float* __restrict__ x,
                      const float* __restrict__ cw,
                      const float* __restrict__ scale,
                      float* __restrict__ out) {
    extern __shared__ char sraw[];
    float4* xs  = (float4*)sraw;                          // [PPB][33]
    float4* cs  = (float4*)(sraw + XS_BYTES);             // [KK][34] rotated
    float*  As  = (float*)(sraw + XS_BYTES + CS_BYTES);   // [PPB][33]
    float*  x2s = As + PPB * AS_STRIDE;                   // [PPB]
    __shared__ int sIsLast;

    const int t    = threadIdx.x;
    const int lane = t & 31;
    const int w    = t >> 5;              // 0..7
    const int b    = blockIdx.x >> 4;
    const int g    = blockIdx.x & 15;
    const int mi   = lane & 1;            // point-subgroup (2 x 4 pts)
    const int ni   = lane >> 1;           // k-pair index (16 pairs)

    // ---- Phase A1: stage x tile; warp w loads complete rows w, w+8, ...
    //      chunk = lane -> fold ||x||^2 reduction into the staging pass ----
    const float4* xg = (const float4*)(x + ((size_t)b * NPTS + (size_t)g * PPB) * DD);
    #pragma unroll
    for (int i = 0; i < 8; ++i) {
        int p = w + 8 * i;
        float4 v = xg[p * 32 + lane];
        xs[p * XS_STRIDE + lane] = v;
        float s2 = v.x * v.x + v.y * v.y + v.z * v.z + v.w * v.w;
        #pragma unroll
        for (int o = 16; o; o >>= 1) s2 += __shfl_xor_sync(0xffffffffu, s2, o);
        if (lane == 0) x2s[p] = s2;
    }

    // ---- Phase A2: augmented codewords w_k = -2*s_k*c_k at slot (d4 + k/2)&31;
    //      slot 32 = (s_k, s_k*||c_k||^2, 0, 0). Warp w builds rows 4w..4w+3. ----
    #pragma unroll
    for (int j = 0; j < 4; ++j) {
        int k = w * 4 + j;
        float4 c = ((const float4*)cw)[k * 32 + lane];
        float s  = scale[k];
        float c2 = c.x * c.x + c.y * c.y + c.z * c.z + c.w * c.w;
        #pragma unroll
        for (int o = 16; o; o >>= 1) c2 += __shfl_xor_sync(0xffffffffu, c2, o);
        float m2 = -2.f * s;
        cs[k * CS_STRIDE + ((lane + (k >> 1)) & 31)] =
            make_float4(m2 * c.x, m2 * c.y, m2 * c.z, m2 * c.w);
        if (lane == 0)
            cs[k * CS_STRIDE + 32] = make_float4(s, s * c2, 0.f, 0.f);
    }
    __syncthreads();

    // ---- Phase C: stage-1 GEMM (logits), 4 pts x 2 k per lane, folded accs ----
    unsigned long long acc[4][2];
    #pragma unroll
    for (int p = 0; p < 4; ++p) { acc[p][0] = 0ull; acc[p][1] = 0ull; }

    const int pbase = w * 8 + mi * 4;
    const ulonglong2* xs2 = (const ulonglong2*)xs;
    const ulonglong2* csrow0 = (const ulonglong2*)cs + (2 * ni + 0) * CS_STRIDE;
    const ulonglong2* csrow1 = (const ulonglong2*)cs + (2 * ni + 1) * CS_STRIDE;

    #pragma unroll 8
    for (int d4 = 0; d4 < 32; ++d4) {
        int cslot = (d4 + ni) & 31;
        ulonglong2 cv0 = csrow0[cslot];
        ulonglong2 cv1 = csrow1[cslot];
        #pragma unroll
        for (int p = 0; p < 4; ++p) {
            ulonglong2 xv = xs2[(pbase + p) * XS_STRIDE + d4];   // linear in d4
            acc[p][0] = ffma2_(cv0.x, xv.x, acc[p][0]);
            acc[p][0] = ffma2_(cv0.y, xv.y, acc[p][0]);
            acc[p][1] = ffma2_(cv1.x, xv.x, acc[p][1]);
            acc[p][1] = ffma2_(cv1.y, xv.y, acc[p][1]);
        }
    }

    float4 cc0 = cs[(2 * ni + 0) * CS_STRIDE + 32];   // (s, s*c2, 0, 0)
    float4 cc1 = cs[(2 * ni + 1) * CS_STRIDE + 32];

    // ---- softmax over K=32 (butterfly on ni bits; mi bit untouched) ----
    #pragma unroll
    for (int p = 0; p < 4; ++p) {
        float x2 = x2s[pbase + p];                     // broadcast LDS
        float2 u0 = unpack2(acc[p][0]);
        float2 u1 = unpack2(acc[p][1]);
        float SL0 = (u0.x + u0.y) + fmaf(cc0.x, x2, cc0.y);
        float SL1 = (u1.x + u1.y) + fmaf(cc1.x, x2, cc1.y);
        float m = fmaxf(SL0, SL1);
        #pragma unroll
        for (int o = 2; o <= 16; o <<= 1) m = fmaxf(m, __shfl_xor_sync(0xffffffffu, m, o));
        float e0 = __expf(SL0 - m);
        float e1 = __expf(SL1 - m);
        float ssum = e0 + e1;
        #pragma unroll
        for (int o = 2; o <= 16; o <<= 1) ssum += __shfl_xor_sync(0xffffffffu, ssum, o);
        float inv = 1.f / ssum;
        As[(pbase + p) * AS_STRIDE + 2 * ni + 0] = e0 * inv;
        As[(pbase + p) * AS_STRIDE + 2 * ni + 1] = e1 * inv;
    }
    __syncthreads();

    // ---- Phase D: E[k][d] = sum_p A[p][k]*x[p][d]; lane=k, warp owns 16 d ----
    unsigned long long acc2[8];
    #pragma unroll
    for (int q = 0; q < 8; ++q) acc2[q] = 0ull;
    float sA = 0.f;
    const int d4b = w * 4;

    #pragma unroll 8
    for (int p = 0; p < PPB; ++p) {
        float a = As[p * AS_STRIDE + lane];            // conflict-free (stride 33)
        sA += a;
        unsigned long long a2 = pack2(a, a);
        #pragma unroll
        for (int q = 0; q < 4; ++q) {
            ulonglong2 xv = xs2[p * XS_STRIDE + d4b + q];   // uniform -> broadcast
            acc2[2 * q + 0] = ffma2_(a2, xv.x, acc2[2 * q + 0]);
            acc2[2 * q + 1] = ffma2_(a2, xv.y, acc2[2 * q + 1]);
        }
    }

    // ---- epilogue: partial tile -> g_Ep[chunk][d][k], coalesced STG.32 ----
    float* ep = (float*)g_Ep4 + (size_t)blockIdx.x * (KK * DD);
    const float4* crow = (const float4*)(cw + (size_t)lane * DD);
    #pragma unroll
    for (int q = 0; q < 4; ++q) {
        int d4 = d4b + q;
        float4 c = crow[d4];
        float2 lo = unpack2(acc2[2 * q + 0]);
        float2 hi = unpack2(acc2[2 * q + 1]);
        ep[(4 * d4 + 0) * KK + lane] = fmaf(-sA, c.x, lo.x);
        ep[(4 * d4 + 1) * KK + lane] = fmaf(-sA, c.y, lo.y);
        ep[(4 * d4 + 2) * KK + lane] = fmaf(-sA, c.z, hi.x);
        ep[(4 * d4 + 3) * KK + lane] = fmaf(-sA, c.w, hi.y);
    }

    // ---- fused cross-CTA reduction: last CTA of each batch sums 16 partials ----
    __threadfence();                                   // release partial stores
    if (t == 0) {
        int old = atomicAdd(&g_cnt[b], 1);
        sIsLast = (old == GPB - 1);
    }
    __syncthreads();

    if (sIsLast) {
        __threadfence();                               // acquire others' stores

        // thread t owns k in [4*(t&7), +4), d in [4*(t>>3), +4)  (16 outputs)
        const int k4 = t & 7;
        const int dg = t >> 3;                         // 0..31
        const float4* base = g_Ep4 + ((size_t)b * GPB) * (KK * DD / 4)
                           + (size_t)(4 * dg) * (KK / 4) + k4;
        float4 s0 = make_float4(0.f, 0.f, 0.f, 0.f);
        float4 s1 = s0, s2 = s0, s3 = s0;
        #pragma unroll 4
        for (int c = 0; c < GPB; ++c) {
            const float4* pc = base + (size_t)c * (KK * DD / 4);
            float4 v0 = pc[0 * (KK / 4)];              // 512B/warp coalesced LDG.128
            float4 v1 = pc[1 * (KK / 4)];
            float4 v2 = pc[2 * (KK / 4)];
            float4 v3 = pc[3 * (KK / 4)];
            s0.x += v0.x; s0.y += v0.y; s0.z += v0.z; s0.w += v0.w;
            s1.x += v1.x; s1.y += v1.y; s1.z += v1.z; s1.w += v1.w;
            s2.x += v2.x; s2.y += v2.y; s2.z += v2.z; s2.w += v2.w;
            s3.x += v3.x; s3.y += v3.y; s3.z += v3.z; s3.w += v3.w;
        }
        // transpose 4x4 (d-major sums -> k-major rows) and store out[b][k][d0..d0+3]
        float4* ob = (float4*)(out + (((size_t)b * KK) + 4 * k4) * DD + 4 * dg);
        ob[0 * (DD / 4)] = make_float4(s0.x, s1.x, s2.x, s3.x);
        ob[1 * (DD / 4)] = make_float4(s0.y, s1.y, s2.y, s3.y);
        ob[2 * (DD / 4)] = make_float4(s0.z, s1.z, s2.z, s3.z);
        ob[3 * (DD / 4)] = make_float4(s0.w, s1.w, s2.w, s3.w);

        if (t == 0) g_cnt[b] = 0;                      // reset for next graph replay
    }
}

extern "C" void kernel_launch(void* const* d_in, const int* in_sizes, int n_in,
                              void* d_out, int out_size) {
    const float* x  = (const float*)d_in[0];   // [16,32,32,128]
    const float* cw = (const float*)d_in[1];   // [32,128]
    const float* sc = (const float*)d_in[2];   // [32]
    float* out = (float*)d_out;                // [16,32,128]

    cudaFuncSetAttribute(ev_encode_kernel,
                         cudaFuncAttributeMaxDynamicSharedMemorySize, SMEM_BYTES);

    ev_encode_kernel<<<NCHUNK, NTHREADS, SMEM_BYTES>>>(x, cw, sc, out);
}